// round 17
// baseline (speedup 1.0000x reference)
#include <cuda_runtime.h>
#include <cuda_fp16.h>
#include <math.h>
#include <stdint.h>

// ---------------- problem constants ----------------
#define QN      40000
#define NCAM    6
#define IMGW    480.0f
#define IMGH    224.0f

#define HW0 6720
#define HW1 1680
#define HW2 420
#define HW3 105
#define TOTPIX 8925

// scratch buffers
__device__ __half g_tfh[(size_t)TOTPIX * NCAM * 128];      // 13.7 MB fp16 features (L2-resident)
__device__ __half g_fvh[(size_t)QN * 1024];                // 81.9 MB fvec (fp16)
__device__ __half g_h1[(size_t)QN * 512];                  // 41 MB
__device__ __half g_h2[(size_t)QN * 512];                  // 41 MB
__device__ __half g_w1t[512 * 1024];                       // weights [N][K] fp16
__device__ __half g_w2t[512 * 512];
__device__ __half g_w3t[512 * 512];
__device__ __half g_w4t[128 * 512];
__device__ __half g_pw2t[128 * 256];                       // pe_w2 [N][K] fp16
__device__ float  g_swb[(size_t)QN * 128];                 // softmaxed scale weights

__device__ __forceinline__ uint32_t f2tf(float x) {
    uint32_t u;
    asm("cvt.rna.tf32.f32 %0, %1;" : "=r"(u) : "f"(x));
    return u;
}
__device__ __forceinline__ void cp16(uint32_t dst, const void* src, bool ok) {
    int sz = ok ? 16 : 0;
    asm volatile("cp.async.cg.shared.global [%0], [%1], 16, %2;"
                 :: "r"(dst), "l"(src), "r"(sz));
}
__device__ __forceinline__ uint32_t pack_h2(float a, float b) {
    __half2 h = __floats2half2_rn(a, b);
    return *(uint32_t*)&h;
}
// half2 (u32) -> packed f32x2 (u64)
__device__ __forceinline__ uint64_t h2f2(uint32_t h) {
    uint64_t u;
    asm("{\n .reg .f16 a,b;\n .reg .f32 lo,hi;\n mov.b32 {a,b}, %1;\n"
        " cvt.f32.f16 lo, a;\n cvt.f32.f16 hi, b;\n mov.b64 %0, {lo,hi};\n}"
        : "=l"(u) : "r"(h));
    return u;
}
__device__ __forceinline__ uint64_t packff(float w) {
    uint64_t u;
    asm("mov.b64 %0, {%1,%1};" : "=l"(u) : "f"(w));
    return u;
}
__device__ __forceinline__ uint64_t fma2(uint64_t a, uint64_t b, uint64_t c) {
    uint64_t d;
    asm("fma.rn.f32x2 %0, %1, %2, %3;" : "=l"(d) : "l"(a), "l"(b), "l"(c));
    return d;
}
__device__ __forceinline__ float2 unpackf2(uint64_t u) {
    float lo, hi;
    asm("mov.b64 {%0,%1}, %2;" : "=f"(lo), "=f"(hi) : "l"(u));
    return make_float2(lo, hi);
}

// ---------------- fused prep: feat transpose (fp32->fp16) + weight round/transpose ----------------
#define S1 (512 * 1024)
#define S2 (512 * 512)
#define S3 (512 * 512)
#define S4 (128 * 512)
#define S5 (128 * 256)
#define RN (S1 + S2 + S3 + S4 + S5)
#define TRBLK 6744   // 281 * 4 * 6

__global__ __launch_bounds__(1024) void prep_all(
    const float* __restrict__ f0, const float* __restrict__ f1,
    const float* __restrict__ f2, const float* __restrict__ f3,
    const float* __restrict__ c1, const float* __restrict__ c2,
    const float* __restrict__ c3, const float* __restrict__ c4,
    const float* __restrict__ pw2)
{
    int bx = blockIdx.x;
    int tid = threadIdx.x;
    if (bx < TRBLK) {
        __shared__ float s[32][33];
        int t  = bx % 281;
        int ch0 = ((bx / 281) & 3) * 32;
        int n  = bx / 1124;
        int trel;
        const float* feat;
        int HW; size_t lbase;
        if (t < 210)      { trel = t;        feat = f0; HW = HW0; lbase = 0; }
        else if (t < 263) { trel = t - 210;  feat = f1; HW = HW1; lbase = (size_t)HW0 * NCAM * 128; }
        else if (t < 277) { trel = t - 263;  feat = f2; HW = HW2; lbase = (size_t)(HW0 + HW1) * NCAM * 128; }
        else              { trel = t - 277;  feat = f3; HW = HW3; lbase = (size_t)(HW0 + HW1 + HW2) * NCAM * 128; }

        int pix0 = trel * 32;
        int tx = tid & 31, ty = tid >> 5;

        int pix = pix0 + tx;
        int ch  = ch0 + ty;
        if (pix < HW)
            s[ty][tx] = feat[((size_t)(n * 128 + ch)) * HW + pix];
        __syncthreads();
        int pixw = pix0 + ty;
        int chw  = ch0 + tx;
        if (pixw < HW)
            g_tfh[lbase + ((size_t)n * HW + pixw) * 128 + chw] = __float2half_rn(s[tx][ty]);
    } else {
        int i = (bx - TRBLK) * 1024 + tid;
        if (i < S1) {
            int n = i >> 10, k = i & 1023;
            g_w1t[i] = __float2half_rn(c1[k * 512 + n]);
        } else if (i < S1 + S2) {
            int j = i - S1; int n = j >> 9, k = j & 511;
            g_w2t[j] = __float2half_rn(c2[k * 512 + n]);
        } else if (i < S1 + S2 + S3) {
            int j = i - S1 - S2; int n = j >> 9, k = j & 511;
            g_w3t[j] = __float2half_rn(c3[k * 512 + n]);
        } else if (i < S1 + S2 + S3 + S4) {
            int j = i - S1 - S2 - S3; int n = j >> 9, k = j & 511;
            g_w4t[j] = __float2half_rn(c4[k * 128 + n]);
        } else if (i < RN) {
            int j = i - S1 - S2 - S3 - S4; int n = j >> 8, k = j & 255;
            g_pw2t[j] = __float2half_rn(pw2[k * 128 + n]);
        }
    }
}

// ---------------- logit GEMM + softmax (tf32) ----------------
__global__ __launch_bounds__(128) void logit_gemm(
    const float* __restrict__ query,
    const float* __restrict__ Wsw,    // [128][16]
    const float* __restrict__ bsw)    // [16]
{
    __shared__ uint32_t As[128 * 36];
    __shared__ uint32_t sW[16 * 132];
    __shared__ float    stg[128 * 20];
    __shared__ float    sb[16];

    const int tid  = threadIdx.x;
    const int lane = tid & 31;
    const int warp = tid >> 5;
    const int bm   = blockIdx.x * 128;

    for (int idx = tid; idx < 2048; idx += 128) {
        int k = idx >> 4, n = idx & 15;
        sW[n * 132 + k] = f2tf(Wsw[k * 16 + n]);
    }
    if (tid < 16) sb[tid] = bsw[tid];

    float c[2][2][4];
    #pragma unroll
    for (int i = 0; i < 2; i++)
        #pragma unroll
        for (int j = 0; j < 2; j++) {
            c[i][j][0] = 0.f; c[i][j][1] = 0.f; c[i][j][2] = 0.f; c[i][j][3] = 0.f;
        }

    for (int k0 = 0; k0 < 128; k0 += 32) {
        __syncthreads();
        #pragma unroll
        for (int i = 0; i < 8; i++) {
            int idx = tid + 128 * i;
            int row = idx >> 3, kq = idx & 7;
            float4 a4 = *(const float4*)(query + (size_t)(bm + row) * 128 + k0 + kq * 4);
            uint32_t* p = &As[row * 36 + kq * 4];
            p[0] = f2tf(a4.x); p[1] = f2tf(a4.y); p[2] = f2tf(a4.z); p[3] = f2tf(a4.w);
        }
        __syncthreads();

        #pragma unroll
        for (int kt = 0; kt < 4; kt++) {
            const int kk = kt * 8 + (lane & 3);
            const int mrow = warp * 32 + (lane >> 2);
            uint32_t a[2][4], b[2][2];
            #pragma unroll
            for (int mt = 0; mt < 2; mt++) {
                int m = mrow + mt * 16;
                a[mt][0] = As[m * 36 + kk];
                a[mt][1] = As[(m + 8) * 36 + kk];
                a[mt][2] = As[m * 36 + kk + 4];
                a[mt][3] = As[(m + 8) * 36 + kk + 4];
            }
            #pragma unroll
            for (int nt = 0; nt < 2; nt++) {
                int n = nt * 8 + (lane >> 2);
                b[nt][0] = sW[n * 132 + k0 + kk];
                b[nt][1] = sW[n * 132 + k0 + kk + 4];
            }
            #pragma unroll
            for (int mt = 0; mt < 2; mt++)
                #pragma unroll
                for (int nt = 0; nt < 2; nt++) {
                    asm volatile(
                        "mma.sync.aligned.m16n8k8.row.col.f32.tf32.tf32.f32 "
                        "{%0,%1,%2,%3}, {%4,%5,%6,%7}, {%8,%9}, {%0,%1,%2,%3};"
                        : "+f"(c[mt][nt][0]), "+f"(c[mt][nt][1]),
                          "+f"(c[mt][nt][2]), "+f"(c[mt][nt][3])
                        : "r"(a[mt][0]), "r"(a[mt][1]), "r"(a[mt][2]), "r"(a[mt][3]),
                          "r"(b[nt][0]), "r"(b[nt][1]));
                }
        }
    }

    __syncthreads();
    #pragma unroll
    for (int mt = 0; mt < 2; mt++) {
        int r0 = warp * 32 + mt * 16 + (lane >> 2);
        #pragma unroll
        for (int nt = 0; nt < 2; nt++) {
            int col = nt * 8 + (lane & 3) * 2;
            #pragma unroll
            for (int half = 0; half < 2; half++) {
                int r = r0 + half * 8;
                stg[r * 20 + col]     = c[mt][nt][half * 2 + 0];
                stg[r * 20 + col + 1] = c[mt][nt][half * 2 + 1];
            }
        }
    }
    __syncthreads();

    {
        int r = tid;
        float v[16];
        #pragma unroll
        for (int j = 0; j < 16; j++) v[j] = stg[r * 20 + j] + sb[j];
        float* op = g_swb + (size_t)(bm + r) * 16;
        #pragma unroll
        for (int gI = 0; gI < 4; gI++) {
            float a = v[gI * 4], b = v[gI * 4 + 1], cc = v[gI * 4 + 2], d = v[gI * 4 + 3];
            float m = fmaxf(fmaxf(a, b), fmaxf(cc, d));
            float ea = expf(a - m), eb = expf(b - m), ec = expf(cc - m), ed = expf(d - m);
            float inv = 1.f / (ea + eb + ec + ed);
            float4 o = make_float4(ea * inv, eb * inv, ec * inv, ed * inv);
            *(float4*)(op + gI * 4) = o;
        }
    }
}

// ---------------- sampling v5: half4 gathers + folded packed weights + f32x2 fma ----------------
__global__ __launch_bounds__(128) void sample_kernel(
    const float* __restrict__ qpos,    // [8][Q][3]
    const float* __restrict__ l2i)     // [6][16]
{
    __shared__ __align__(16) float s_sw[128];
    __shared__ float s_l2i[96];
    __shared__ float s_qp[8][3];
    __shared__ float s_u[8], s_v[8];
    __shared__ int   s_cam[8], s_ok[8];
    __shared__ __align__(16) int      s_off[8][4][4];
    __shared__ __align__(16) float    s_wtr[8][4][4];        // raw bilinear weights
    __shared__ __align__(16) uint64_t s_wtf[8][4][4][4];     // packed folded [p][l][g][corner]

    const int q   = blockIdx.x;
    const int tid = threadIdx.x;

    if (tid < 32) ((float4*)s_sw)[tid] = ((const float4*)(g_swb + (size_t)q * 128))[tid];
    if (tid < 96) s_l2i[tid] = l2i[tid];
    if (tid < 24) s_qp[tid / 3][tid % 3] = qpos[((size_t)(tid / 3) * QN + q) * 3 + (tid % 3)];
    __syncthreads();

    if (tid < 8) {
        int p = tid;
        float X = s_qp[p][0] * 100.f - 50.f;
        float Y = s_qp[p][1] * 100.f - 50.f;
        float Zc = s_qp[p][2] * 8.f - 4.f;
        int found = 0, cam = 0; float uu = 0.f, vv = 0.f;
        #pragma unroll
        for (int n = 0; n < 6; n++) {
            const float* M = s_l2i + n * 16;
            float c0 = M[0] * X + M[1] * Y + M[2]  * Zc + M[3];
            float c1 = M[4] * X + M[5] * Y + M[6]  * Zc + M[7];
            float c2 = M[8] * X + M[9] * Y + M[10] * Zc + M[11];
            float den = fmaxf(c2, 1e-6f);
            float u = (c0 / den) / IMGW;
            float v = (c1 / den) / IMGH;
            bool val = (c2 > 1e-6f) && (u > 0.f) && (u < 1.f) && (v > 0.f) && (v < 1.f);
            if (val && !found) { found = 1; cam = n; uu = u; vv = v; }
        }
        s_cam[p] = cam; s_ok[p] = found; s_u[p] = uu; s_v[p] = vv;
    }
    __syncthreads();

    if (tid < 32) {
        int p = tid >> 2, l = tid & 3;
        int4 off = make_int4(-1, -1, -1, -1);
        float4 wt = make_float4(0.f, 0.f, 0.f, 0.f);
        if (s_ok[p]) {
            const int LW[4]    = {120, 60, 30, 15};
            const int LH[4]    = {56, 28, 14, 7};
            const int LHW[4]   = {HW0, HW1, HW2, HW3};
            const int LBASE[4] = {0, HW0 * NCAM * 128, (HW0 + HW1) * NCAM * 128, (HW0 + HW1 + HW2) * NCAM * 128};
            int w = LW[l], h = LH[l];
            int base = LBASE[l] + s_cam[p] * LHW[l] * 128;
            float x = s_u[p] * (float)w - 0.5f;
            float y = s_v[p] * (float)h - 0.5f;
            float xf = floorf(x), yf = floorf(y);
            float wx = x - xf, wy = y - yf;
            int x0 = (int)xf, y0 = (int)yf;
            int x1 = x0 + 1, y1 = y0 + 1;
            bool ix0 = (x0 >= 0) && (x0 < w);
            bool ix1 = (x1 < w);
            bool iy0 = (y0 >= 0) && (y0 < h);
            bool iy1 = (y1 < h);
            if (iy0 && ix0) off.x = base + (y0 * w + x0) * 128;
            if (iy0 && ix1) off.y = base + (y0 * w + x1) * 128;
            if (iy1 && ix0) off.z = base + (y1 * w + x0) * 128;
            if (iy1 && ix1) off.w = base + (y1 * w + x1) * 128;
            wt.x = (1.f - wx) * (1.f - wy);
            wt.y = wx * (1.f - wy);
            wt.z = (1.f - wx) * wy;
            wt.w = wx * wy;
        }
        *(int4*)&s_off[p][l][0] = off;
        *(float4*)&s_wtr[p][l][0] = wt;
    }
    __syncthreads();

    // fold softmax scale into packed corner weights
    {
        int p = tid >> 4, lg = tid & 15, l = lg >> 2, g = lg & 3;
        float swl = s_sw[p * 16 + g * 4 + l];
        float4 wr = *(const float4*)&s_wtr[p][l][0];
        s_wtf[p][l][g][0] = packff(wr.x * swl);
        s_wtf[p][l][g][1] = packff(wr.y * swl);
        s_wtf[p][l][g][2] = packff(wr.z * swl);
        s_wtf[p][l][g][3] = packff(wr.w * swl);
    }
    __syncthreads();

    // gather: thread = (ph 0..3 covering 2 p's, c4 0..31 covering 4 channels)
    const int c4 = tid & 31;
    const int ph = tid >> 5;
    const int g  = c4 >> 3;
    const __half* tf = g_tfh;

    #pragma unroll
    for (int pi = 0; pi < 2; pi++) {
        int p = ph * 2 + pi;
        uint64_t s01 = 0ULL, s23 = 0ULL;
        #pragma unroll
        for (int l = 0; l < 4; l++) {
            int4 o = *(const int4*)&s_off[p][l][0];
            const uint64_t* wf = &s_wtf[p][l][g][0];
            if (o.x >= 0) {
                uint2 r = *(const uint2*)(tf + o.x + c4 * 4);
                uint64_t w = wf[0];
                s01 = fma2(h2f2(r.x), w, s01);
                s23 = fma2(h2f2(r.y), w, s23);
            }
            if (o.y >= 0) {
                uint2 r = *(const uint2*)(tf + o.y + c4 * 4);
                uint64_t w = wf[1];
                s01 = fma2(h2f2(r.x), w, s01);
                s23 = fma2(h2f2(r.y), w, s23);
            }
            if (o.z >= 0) {
                uint2 r = *(const uint2*)(tf + o.z + c4 * 4);
                uint64_t w = wf[2];
                s01 = fma2(h2f2(r.x), w, s01);
                s23 = fma2(h2f2(r.y), w, s23);
            }
            if (o.w >= 0) {
                uint2 r = *(const uint2*)(tf + o.w + c4 * 4);
                uint64_t w = wf[3];
                s01 = fma2(h2f2(r.x), w, s01);
                s23 = fma2(h2f2(r.y), w, s23);
            }
        }
        float2 f01 = unpackf2(s01);
        float2 f23 = unpackf2(s23);
        uint2 outv;
        outv.x = pack_h2(f01.x, f01.y);
        outv.y = pack_h2(f23.x, f23.y);
        *(uint2*)(g_fvh + (size_t)q * 1024 + p * 128 + c4 * 4) = outv;
    }
}

// ---------------- fp16 GEMM: BK=64, 3-stage cp.async, 128 thr, 64x64 warp tiles ----------------
#define ASZH (128 * 36)
#define BSZH (128 * 36)
#define STGH (ASZH + BSZH)
#define NSTG 3

template <int RELU, int TROUT>
__global__ __launch_bounds__(128, 2) void mma_gemm_h(
    const __half* __restrict__ A, const __half* __restrict__ W,
    const float* __restrict__ bias, void* Cout,
    int M, int K, int N)
{
    extern __shared__ uint32_t sm[];

    const int tid  = threadIdx.x;
    const int lane = tid & 31;
    const int warp = tid >> 5;
    const int wm = warp >> 1;
    const int wn = warp & 1;
    const int bn = blockIdx.x * 128, bm = blockIdx.y * 128;

    float c[4][8][4];
    #pragma unroll
    for (int i = 0; i < 4; i++)
        #pragma unroll
        for (int j = 0; j < 8; j++) {
            c[i][j][0] = 0.f; c[i][j][1] = 0.f; c[i][j][2] = 0.f; c[i][j][3] = 0.f;
        }

    uint32_t as_base[NSTG], bs_base[NSTG];
    #pragma unroll
    for (int s = 0; s < NSTG; s++) {
        as_base[s] = (uint32_t)__cvta_generic_to_shared(sm + s * STGH);
        bs_base[s] = (uint32_t)__cvta_generic_to_shared(sm + s * STGH + ASZH);
    }

    auto load_slab = [&](int k0, int s) {
        #pragma unroll
        for (int i = 0; i < 8; i++) {
            int idx = tid + 128 * i;
            int row = idx >> 3, kq = idx & 7;
            bool ok = (bm + row) < M;
            const __half* src = A + (size_t)(bm + (ok ? row : 0)) * K + k0 + kq * 8;
            cp16(as_base[s] + (row * 36 + kq * 4) * 4, src, ok);
        }
        #pragma unroll
        for (int i = 0; i < 8; i++) {
            int idx = tid + 128 * i;
            int n = idx >> 3, kq = idx & 7;
            const __half* src = W + (size_t)(bn + n) * K + k0 + kq * 8;
            cp16(bs_base[s] + (n * 36 + kq * 4) * 4, src, true);
        }
    };

    const int nslab = K >> 6;
    load_slab(0, 0);
    asm volatile("cp.async.commit_group;");
    if (nslab > 1) load_slab(64, 1);
    asm volatile("cp.async.commit_group;");

    for (int i = 0; i < nslab; i++) {
        asm volatile("cp.async.wait_group 1;");
        __syncthreads();

        if (i + 2 < nslab) load_slab((i + 2) << 6, (i + 2) % NSTG);
        asm volatile("cp.async.commit_group;");

        const int s = i % NSTG;
        const uint32_t* As = sm + s * STGH;
        const uint32_t* Bs = sm + s * STGH + ASZH;

        #pragma unroll
        for (int kc = 0; kc < 4; kc++) {
            const int base = kc * 8 + (lane & 3);
            uint32_t a[4][4], b[8][2];
            const int mrow = wm * 64 + (lane >> 2);
            #pragma unroll
            for (int mt = 0; mt < 4; mt++) {
                int m = mrow + mt * 16;
                a[mt][0] = As[m * 36 + base];
                a[mt][1] = As[(m + 8) * 36 + base];
                a[mt][2] = As[m * 36 + base + 4];
                a[mt][3] = As[(m + 8) * 36 + base + 4];
            }
            const int nc = wn * 64 + (lane >> 2);
            #pragma unroll
            for (int nt = 0; nt < 8; nt++) {
                int n = nc + nt * 8;
                b[nt][0] = Bs[n * 36 + base];
                b[nt][1] = Bs[n * 36 + base + 4];
            }
            #pragma unroll
            for (int mt = 0; mt < 4; mt++)
                #pragma unroll
                for (int nt = 0; nt < 8; nt++) {
                    asm volatile(
                        "mma.sync.aligned.m16n8k16.row.col.f32.f16.f16.f32 "
                        "{%0,%1,%2,%3}, {%4,%5,%6,%7}, {%8,%9}, {%0,%1,%2,%3};"
                        : "+f"(c[mt][nt][0]), "+f"(c[mt][nt][1]),
                          "+f"(c[mt][nt][2]), "+f"(c[mt][nt][3])
                        : "r"(a[mt][0]), "r"(a[mt][1]), "r"(a[mt][2]), "r"(a[mt][3]),
                          "r"(b[nt][0]), "r"(b[nt][1]));
                }
        }
    }

    if (!TROUT) {
        __half* C = (__half*)Cout;
        #pragma unroll
        for (int mt = 0; mt < 4; mt++) {
            int row0 = bm + wm * 64 + mt * 16 + (lane >> 2);
            #pragma unroll
            for (int nt = 0; nt < 8; nt++) {
                int col = bn + wn * 64 + nt * 8 + (lane & 3) * 2;
                float b0 = bias[col], b1 = bias[col + 1];
                #pragma unroll
                for (int half = 0; half < 2; half++) {
                    int row = row0 + half * 8;
                    if (row < M) {
                        float v0 = c[mt][nt][half * 2 + 0] + b0;
                        float v1 = c[mt][nt][half * 2 + 1] + b1;
                        if (RELU) { v0 = fmaxf(v0, 0.f); v1 = fmaxf(v1, 0.f); }
                        __half2 hv = __floats2half2_rn(v0, v1);
                        *(__half2*)(C + (size_t)row * N + col) = hv;
                    }
                }
            }
        }
    } else {
        float* C = (float*)Cout;
        asm volatile("cp.async.wait_group 0;");
        __syncthreads();
        float* stg = (float*)sm;   // [128 rows][132]
        #pragma unroll
        for (int mt = 0; mt < 4; mt++) {
            int r0 = wm * 64 + mt * 16 + (lane >> 2);
            #pragma unroll
            for (int nt = 0; nt < 8; nt++) {
                int col = wn * 64 + nt * 8 + (lane & 3) * 2;
                float b0 = bias[col], b1 = bias[col + 1];
                #pragma unroll
                for (int half = 0; half < 2; half++) {
                    int r = r0 + half * 8;
                    stg[r * 132 + col]     = c[mt][nt][half * 2 + 0] + b0;
                    stg[r * 132 + col + 1] = c[mt][nt][half * 2 + 1] + b1;
                }
            }
        }
        __syncthreads();
        #pragma unroll
        for (int i = 0; i < 32; i++) {
            int idx = i * 128 + tid;
            int col = idx >> 5;
            int r4  = idx & 31;
            int row = bm + r4 * 4;
            float4 v;
            v.x = stg[(r4 * 4 + 0) * 132 + col];
            v.y = stg[(r4 * 4 + 1) * 132 + col];
            v.z = stg[(r4 * 4 + 2) * 132 + col];
            v.w = stg[(r4 * 4 + 3) * 132 + col];
            if (row + 3 < M) {
                *(float4*)(C + (size_t)col * M + row) = v;
            } else {
                if (row + 0 < M) C[(size_t)col * M + row + 0] = v.x;
                if (row + 1 < M) C[(size_t)col * M + row + 1] = v.y;
                if (row + 2 < M) C[(size_t)col * M + row + 2] = v.z;
                if (row + 3 < M) C[(size_t)col * M + row + 3] = v.w;
            }
        }
    }
}

// ---------------- fp16 PE GEMM: fvh += relu(qp@W1+b1)@W2 + b2 ----------------
__global__ __launch_bounds__(256, 2) void pe_gemm_h(
    const float* __restrict__ qpos,    // [8][Q][3]
    const float* __restrict__ pew1,    // [3][256]
    const float* __restrict__ peb1,    // [256]
    const float* __restrict__ peb2)    // [128]
{
    __shared__ __align__(16) uint32_t AsBs[ASZH + BSZH];
    uint32_t* As = AsBs;
    uint32_t* Bs = AsBs + ASZH;
    float* stg = (float*)AsBs;
    __shared__ float sw1[768];
    __shared__ float sb1[256];
    __shared__ float s_pb2[128];
    __shared__ float sxyz[128 * 3];

    const int tid  = threadIdx.x;
    const int lane = tid & 31;
    const int warp = tid >> 5;
    const int wm = warp >> 2;
    const int wn = warp & 3;
    const int bm = blockIdx.x * 128;

    sw1[tid] = pew1[tid]; sw1[tid + 256] = pew1[tid + 256]; sw1[tid + 512] = pew1[tid + 512];
    if (tid < 256) sb1[tid] = peb1[tid];
    if (tid < 128) s_pb2[tid] = peb2[tid];
    if (tid < 128) {
        int r = bm + tid;
        int q = r >> 3, p = r & 7;
        const float* xp = qpos + ((size_t)p * QN + q) * 3;
        sxyz[tid * 3 + 0] = xp[0];
        sxyz[tid * 3 + 1] = xp[1];
        sxyz[tid * 3 + 2] = xp[2];
    }

    float c[4][4][4];
    #pragma unroll
    for (int i = 0; i < 4; i++)
        #pragma unroll
        for (int j = 0; j < 4; j++) {
            c[i][j][0] = 0.f; c[i][j][1] = 0.f; c[i][j][2] = 0.f; c[i][j][3] = 0.f;
        }

    const int am = tid >> 3, akq = tid & 7;

    __syncthreads();

    for (int k0 = 0; k0 < 256; k0 += 64) {
        __syncthreads();
        #pragma unroll
        for (int i = 0; i < 4; i++) {
            int m = am + 32 * i;
            float x0 = sxyz[m * 3], x1 = sxyz[m * 3 + 1], x2 = sxyz[m * 3 + 2];
            uint32_t* p = &As[m * 36 + akq * 4];
            #pragma unroll
            for (int t = 0; t < 4; t++) {
                int j0 = k0 + akq * 8 + t * 2;
                float h0 = fmaxf(sb1[j0] + x0 * sw1[j0] + x1 * sw1[256 + j0] + x2 * sw1[512 + j0], 0.f);
                int j1 = j0 + 1;
                float h1 = fmaxf(sb1[j1] + x0 * sw1[j1] + x1 * sw1[256 + j1] + x2 * sw1[512 + j1], 0.f);
                p[t] = pack_h2(h0, h1);
            }
        }
        #pragma unroll
        for (int i = 0; i < 4; i++) {
            int idx = tid + 256 * i;
            int n = idx >> 3, kq = idx & 7;
            const float4 b4 = *(const float4*)((const __half*)g_pw2t + (size_t)n * 256 + k0 + kq * 8);
            uint32_t* p = &Bs[n * 36 + kq * 4];
            const uint32_t* bu = (const uint32_t*)&b4;
            p[0] = bu[0]; p[1] = bu[1]; p[2] = bu[2]; p[3] = bu[3];
        }
        __syncthreads();

        #pragma unroll
        for (int kc = 0; kc < 4; kc++) {
            const int base = kc * 8 + (lane & 3);
            uint32_t a[4][4], b[4][2];
            const int mrow = wm * 64 + (lane >> 2);
            #pragma unroll
            for (int mt = 0; mt < 4; mt++) {
                int m = mrow + mt * 16;
                a[mt][0] = As[m * 36 + base];
                a[mt][1] = As[(m + 8) * 36 + base];
                a[mt][2] = As[m * 36 + base + 4];
                a[mt][3] = As[(m + 8) * 36 + base + 4];
            }
            const int nc = wn * 32 + (lane >> 2);
            #pragma unroll
            for (int nt = 0; nt < 4; nt++) {
                int n = nc + nt * 8;
                b[nt][0] = Bs[n * 36 + base];
                b[nt][1] = Bs[n * 36 + base + 4];
            }
            #pragma unroll
            for (int mt = 0; mt < 4; mt++)
                #pragma unroll
                for (int nt = 0; nt < 4; nt++) {
                    asm volatile(
                        "mma.sync.aligned.m16n8k16.row.col.f32.f16.f16.f32 "
                        "{%0,%1,%2,%3}, {%4,%5,%6,%7}, {%8,%9}, {%0,%1,%2,%3};"
                        : "+f"(c[mt][nt][0]), "+f"(c[mt][nt][1]),
                          "+f"(c[mt][nt][2]), "+f"(c[mt][nt][3])
                        : "r"(a[mt][0]), "r"(a[mt][1]), "r"(a[mt][2]), "r"(a[mt][3]),
                          "r"(b[nt][0]), "r"(b[nt][1]));
                }
        }
    }

    #pragma unroll
    for (int h = 0; h < 2; h++) {
        __syncthreads();
        if (wm == h) {
            #pragma unroll
            for (int mt = 0; mt < 4; mt++) {
                int r0 = mt * 16 + (lane >> 2);
                #pragma unroll
                for (int nt = 0; nt < 4; nt++) {
                    int col = wn * 32 + nt * 8 + (lane & 3) * 2;
                    #pragma unroll
                    for (int half8 = 0; half8 < 2; half8++) {
                        int r = r0 + half8 * 8;
                        stg[r * 132 + col]     = c[mt][nt][half8 * 2 + 0];
                        stg[r * 132 + col + 1] = c[mt][nt][half8 * 2 + 1];
                    }
                }
            }
        }
        __syncthreads();
        #pragma unroll
        for (int i = 0; i < 16; i++) {
            int idx = tid + 256 * i;
            int r  = idx >> 6;
            int c2 = idx & 63;
            __half2* gp = (__half2*)(g_fvh + (size_t)(bm + h * 64 + r) * 128) + c2;
            float2 f = __half22float2(*gp);
            float o0 = f.x + stg[r * 132 + c2 * 2]     + s_pb2[c2 * 2];
            float o1 = f.y + stg[r * 132 + c2 * 2 + 1] + s_pb2[c2 * 2 + 1];
            *gp = __floats2half2_rn(o0, o1);
        }
    }
}

// ---------------- launch ----------------
extern "C" void kernel_launch(void* const* d_in, const int* in_sizes, int n_in,
                              void* d_out, int out_size) {
    const float* feat0 = (const float*)d_in[0];
    const float* feat1 = (const float*)d_in[1];
    const float* feat2 = (const float*)d_in[2];
    const float* feat3 = (const float*)d_in[3];
    const float* query = (const float*)d_in[4];
    const float* qpos  = (const float*)d_in[5];
    const float* l2i   = (const float*)d_in[6];
    const float* Wsw   = (const float*)d_in[7];
    const float* bsw   = (const float*)d_in[8];
    const float* pew1  = (const float*)d_in[9];
    const float* peb1  = (const float*)d_in[10];
    const float* pew2  = (const float*)d_in[11];
    const float* peb2  = (const float*)d_in[12];
    const float* cw1   = (const float*)d_in[13];
    const float* cb1   = (const float*)d_in[14];
    const float* cw2   = (const float*)d_in[15];
    const float* cb2   = (const float*)d_in[16];
    const float* cw3   = (const float*)d_in[17];
    const float* cb3   = (const float*)d_in[18];
    const float* cw4   = (const float*)d_in[19];
    const float* cb4   = (const float*)d_in[20];
    float* out = (float*)d_out;

    __half* fv;  cudaGetSymbolAddress((void**)&fv,  g_fvh);
    __half* h1;  cudaGetSymbolAddress((void**)&h1,  g_h1);
    __half* h2;  cudaGetSymbolAddress((void**)&h2,  g_h2);
    __half* w1;  cudaGetSymbolAddress((void**)&w1,  g_w1t);
    __half* w2;  cudaGetSymbolAddress((void**)&w2,  g_w2t);
    __half* w3;  cudaGetSymbolAddress((void**)&w3,  g_w3t);
    __half* w4;  cudaGetSymbolAddress((void**)&w4,  g_w4t);

    const size_t dsmem = (size_t)STGH * NSTG * 4;   // 108 KB
    cudaFuncSetAttribute(mma_gemm_h<1, 0>, cudaFuncAttributeMaxDynamicSharedMemorySize, (int)dsmem);
    cudaFuncSetAttribute(mma_gemm_h<0, 1>, cudaFuncAttributeMaxDynamicSharedMemorySize, (int)dsmem);

    // launch 0: fused feat transpose + weight prep
    prep_all<<<TRBLK + (RN + 1023) / 1024, 1024>>>(feat0, feat1, feat2, feat3,
                                                   cw1, cw2, cw3, cw4, pew2);

    // launch 1: scale-weight logits + softmax
    logit_gemm<<<QN * 8 / 128, 128>>>(query, Wsw, bsw);

    // launch 2: sampling -> fvh
    sample_kernel<<<QN, 128>>>(qpos, l2i);

    // launch 3 (ncu capture slot): fvh += pos_emb + b2
    pe_gemm_h<<<QN * 8 / 128, 256>>>(qpos, pew1, peb1, peb2);

    // launches 4-7: compressor GEMMs (fp16); last writes transposed fp32 out
    const int MB = (QN + 127) / 128; // 313
    mma_gemm_h<1, 0><<<dim3(4, MB), 128, dsmem>>>(fv, w1, cb1, h1, QN, 1024, 512);
    mma_gemm_h<1, 0><<<dim3(4, MB), 128, dsmem>>>(h1, w2, cb2, h2, QN, 512, 512);
    mma_gemm_h<1, 0><<<dim3(4, MB), 128, dsmem>>>(h2, w3, cb3, h1, QN, 512, 512);
    mma_gemm_h<0, 1><<<dim3(1, MB), 128, dsmem>>>(h1, w4, cb4, out, QN, 512, 128);
}